// round 2
// baseline (speedup 1.0000x reference)
#include <cuda_runtime.h>
#include <math.h>

#define Hdim 384
#define Wdim 384
#define HWp  (Hdim*Wdim)
#define BATCH 8
#define NTOT (BATCH*HWp)
#define PER_IMG (2*Wdim + 2*(Hdim-2))   // 1532 border pixels per image

// Scratch (static device globals; no runtime allocation)
__device__ float g_F[9 * NTOT];       // 9 feature planes: silu, bases[0..7]
__device__ float g_G[16 * 3 * 3 * 9]; // G[c][di][dj][m]
__device__ float g_H[9 * 25];         // composed 5x5 weights H[m][du][dv]
__device__ float g_F0[9];             // features of padded zero: [0, B0(0)..B7(0)]

// Cox-de Boor cubic bases on the fixed grid (h = 0.4, knots (i-3)*0.4-1),
// identical recursion to the reference. Writes 8 bases to b8.
__device__ __forceinline__ void spline_bases(float v, float* b8)
{
    float b[11];
#pragma unroll
    for (int i = 0; i < 11; i++) {
        float gi  = (i - 3) * 0.4f - 1.0f;
        float gi1 = (i - 2) * 0.4f - 1.0f;
        b[i] = (v >= gi && v < gi1) ? 1.f : 0.f;
    }
#pragma unroll
    for (int k = 1; k <= 3; k++) {
        float rinv = 1.0f / (0.4f * (float)k);
#pragma unroll
        for (int i = 0; i + k < 11; i++) {
            float gi   = (i - 3) * 0.4f - 1.0f;          // g[i]
            float gik1 = (i + k - 2) * 0.4f - 1.0f;      // g[i+k+1]
            b[i] = (v - gi) * rinv * b[i] + (gik1 - v) * rinv * b[i + 1];
        }
    }
#pragma unroll
    for (int m = 0; m < 8; m++) b8[m] = b[m];
}

// ---------------------------------------------------------------------------
// Kernel 0: build G (per-conv 3x3x9 weights), composed H = restore_w (*) G,
// and F0 (feature vector of a zero-padded input sample).
// Single block so __syncthreads orders G before H.
// ---------------------------------------------------------------------------
__global__ void prep_kernel(const float* __restrict__ bw,   // [16,9]
                            const float* __restrict__ sw,   // [16,9,8]
                            const float* __restrict__ ss,   // [16,9]
                            const float* __restrict__ rw)   // [1,16,3,3]
{
    int t = threadIdx.x;
    for (int idx = t; idx < 16 * 81; idx += blockDim.x) {
        int c = idx / 81, r = idx % 81;
        int di = r / 27, dj = (r / 9) % 3, m = r % 9;
        int k = di * 3 + dj;
        float val;
        if (m == 0) val = bw[c * 9 + k];
        else        val = sw[(c * 9 + k) * 8 + (m - 1)] * ss[c * 9 + k];
        g_G[((c * 3 + di) * 3 + dj) * 9 + m] = val;
    }
    if (t == 0) {
        float b8[8];
        spline_bases(0.0f, b8);
        g_F0[0] = 0.0f;                 // silu(0)
        for (int m = 0; m < 8; m++) g_F0[m + 1] = b8[m];
    }
    __syncthreads();
    for (int idx = t; idx < 225; idx += blockDim.x) {
        int m = idx / 25, r = idx % 25;
        int du = r / 5, dv = r % 5;
        float s = 0.f;
        for (int c = 0; c < 16; c++)
            for (int u = 0; u < 3; u++) {
                int di = du - u; if (di < 0 || di > 2) continue;
                for (int v = 0; v < 3; v++) {
                    int dj = dv - v; if (dj < 0 || dj > 2) continue;
                    s += rw[(c * 3 + u) * 3 + v] * g_G[((c * 3 + di) * 3 + dj) * 9 + m];
                }
            }
        g_H[idx] = s;
    }
}

// ---------------------------------------------------------------------------
// Kernel 1: per-pixel features. f0 = silu(x), f1..f8 = cubic B-spline bases.
// ---------------------------------------------------------------------------
__global__ void feat_kernel(const float* __restrict__ x)
{
    int n = blockIdx.x * blockDim.x + threadIdx.x;
    if (n >= NTOT) return;
    float v = x[n];

    float sig = 1.0f / (1.0f + expf(-v));
    g_F[n] = v * sig;

    float b8[8];
    spline_bases(v, b8);
#pragma unroll
    for (int m = 0; m < 8; m++)
        g_F[(size_t)(m + 1) * NTOT + n] = b8[m];
}

// ---------------------------------------------------------------------------
// Kernel 2: composed 5x5 conv over 9 feature channels -> out (interior-exact).
// 64 threads/block, each computes a 4x4 output micro-tile; block tile 32x32.
// Out-of-image feature values are F0 (features of the zero-padded input).
// ---------------------------------------------------------------------------
__global__ void __launch_bounds__(64) main_kernel(float* __restrict__ out,
                                                  const float* __restrict__ rb)
{
    __shared__ float sF[36 * 40];   // 36x36 tile, row stride 40 (float4-friendly)
    __shared__ float sH[225];

    int t  = threadIdx.x;
    int tx = t & 7, ty = t >> 3;
    int gx0 = blockIdx.x * 32, gy0 = blockIdx.y * 32;
    int bz = blockIdx.z;

    for (int i = t; i < 225; i += 64) sH[i] = g_H[i];

    float acc[4][4] = {};
    const float* Fbase = g_F + (size_t)bz * HWp;

#pragma unroll 1
    for (int m = 0; m < 9; m++) {
        float f0 = g_F0[m];
        __syncthreads();
        const float* Fp = Fbase + (size_t)m * NTOT;
        for (int idx = t; idx < 36 * 36; idx += 64) {
            int r = idx / 36, c2 = idx - r * 36;
            int gy = gy0 - 2 + r, gx = gx0 - 2 + c2;
            float val = f0;
            if (gy >= 0 && gy < Hdim && gx >= 0 && gx < Wdim)
                val = __ldg(&Fp[gy * Wdim + gx]);
            sF[r * 40 + c2] = val;
        }
        __syncthreads();

        float win[8][8];
#pragma unroll
        for (int dy = 0; dy < 8; dy++) {
            const float* row = &sF[(ty * 4 + dy) * 40 + tx * 4];
            float4 a = *(const float4*)(row);
            float4 bq = *(const float4*)(row + 4);
            win[dy][0] = a.x;  win[dy][1] = a.y;  win[dy][2] = a.z;  win[dy][3] = a.w;
            win[dy][4] = bq.x; win[dy][5] = bq.y; win[dy][6] = bq.z; win[dy][7] = bq.w;
        }

        const float* Hm = &sH[m * 25];
#pragma unroll
        for (int du = 0; du < 5; du++)
#pragma unroll
            for (int dv = 0; dv < 5; dv++) {
                float h = Hm[du * 5 + dv];
#pragma unroll
                for (int ry = 0; ry < 4; ry++)
#pragma unroll
                    for (int rx = 0; rx < 4; rx++)
                        acc[ry][rx] = fmaf(h, win[ry + du][rx + dv], acc[ry][rx]);
            }
    }

    float rbv = __ldg(rb);
    float* op = out + (size_t)bz * HWp;
#pragma unroll
    for (int ry = 0; ry < 4; ry++) {
        int oy = gy0 + ty * 4 + ry;
        float4 o;
        o.x = acc[ry][0] + rbv; o.y = acc[ry][1] + rbv;
        o.z = acc[ry][2] + rbv; o.w = acc[ry][3] + rbv;
        *(float4*)&op[(size_t)oy * Wdim + gx0 + tx * 4] = o;
    }
}

// ---------------------------------------------------------------------------
// Kernel 3: honest two-stage path for the 1-pixel output border (overwrites).
// 16 lanes per pixel (one per conv channel c), shfl reduce.
// y outside the image is zero (restore conv zero-pads y); features outside
// the image are F0 (features of the zero-padded x).
// ---------------------------------------------------------------------------
__global__ void border_kernel(float* __restrict__ out,
                              const float* __restrict__ rw,
                              const float* __restrict__ rb)
{
    int tid = blockIdx.x * blockDim.x + threadIdx.x;
    int c = tid & 15;
    int pix = tid >> 4;
    if (pix >= BATCH * PER_IMG) return;
    int b = pix / PER_IMG, e = pix % PER_IMG;
    int i, j;
    if (e < Wdim)            { i = 0;        j = e; }
    else if (e < 2 * Wdim)   { i = Hdim - 1; j = e - Wdim; }
    else if (e < 2 * Wdim + (Hdim - 2)) { i = e - 2 * Wdim + 1; j = 0; }
    else                     { i = e - (2 * Wdim + (Hdim - 2)) + 1; j = Wdim - 1; }

    const float* Fb = g_F + (size_t)b * HWp;
    float acc = 0.f;
    for (int u = 0; u < 3; u++) {
        int yi = i + u - 1; if (yi < 0 || yi >= Hdim) continue;
        for (int v = 0; v < 3; v++) {
            int yj = j + v - 1; if (yj < 0 || yj >= Wdim) continue;
            float yv = 0.f;
            for (int di = 0; di < 3; di++) {
                int fi = yi + di - 1;
                for (int dj = 0; dj < 3; dj++) {
                    int fj = yj + dj - 1;
                    bool inb = (fi >= 0 && fi < Hdim && fj >= 0 && fj < Wdim);
                    const float* Gp = &g_G[((c * 3 + di) * 3 + dj) * 9];
                    size_t fo = (size_t)fi * Wdim + fj;
#pragma unroll
                    for (int m = 0; m < 9; m++) {
                        float fv = inb ? Fb[(size_t)m * NTOT + fo] : g_F0[m];
                        yv = fmaf(__ldg(&Gp[m]), fv, yv);
                    }
                }
            }
            acc = fmaf(__ldg(&rw[(c * 3 + u) * 3 + v]), yv, acc);
        }
    }
#pragma unroll
    for (int o = 8; o >= 1; o >>= 1)
        acc += __shfl_xor_sync(0xffffffffu, acc, o);
    if (c == 0)
        out[(size_t)b * HWp + (size_t)i * Wdim + j] = acc + __ldg(rb);
}

// ---------------------------------------------------------------------------
extern "C" void kernel_launch(void* const* d_in, const int* in_sizes, int n_in,
                              void* d_out, int out_size)
{
    const float* x  = (const float*)d_in[0];
    const float* bw = (const float*)d_in[1];
    const float* sw = (const float*)d_in[2];
    const float* ss = (const float*)d_in[3];
    const float* rw = (const float*)d_in[4];
    const float* rb = (const float*)d_in[5];
    float* out = (float*)d_out;

    prep_kernel<<<1, 256>>>(bw, sw, ss, rw);
    feat_kernel<<<(NTOT + 255) / 256, 256>>>(x);
    dim3 grid(Wdim / 32, Hdim / 32, BATCH);
    main_kernel<<<grid, 64>>>(out, rb);
    int border_threads = BATCH * PER_IMG * 16;
    border_kernel<<<(border_threads + 255) / 256, 256>>>(out, rw, rb);
}

// round 3
// speedup vs baseline: 1.9056x; 1.9056x over previous
#include <cuda_runtime.h>
#include <math.h>

#define Hdim 384
#define Wdim 384
#define HWp  (Hdim*Wdim)
#define BATCH 8
#define NTOT (BATCH*HWp)
#define PER_IMG (2*Wdim + 2*(Hdim-2))   // 1532 border pixels per image
#define NBORD  (BATCH*PER_IMG)

// Scratch (static device globals; no runtime allocation)
__device__ float g_G[16 * 3 * 3 * 9];   // G[c][di][dj][m] (prep-internal)
__device__ float g_Hc[9][9 * 25];       // per-border-class composed weights [cls][m][du*5+dv]

// Cox-de Boor cubic bases on the fixed grid (h = 0.4, knots (i-3)*0.4-1),
// identical recursion to the reference. Writes 8 bases to b8.
// Note: spline_bases(0) gives exactly the padded-zero feature vector.
__device__ __forceinline__ void spline_bases(float v, float* b8)
{
    float b[11];
#pragma unroll
    for (int i = 0; i < 11; i++) {
        float gi  = (i - 3) * 0.4f - 1.0f;
        float gi1 = (i - 2) * 0.4f - 1.0f;
        b[i] = (v >= gi && v < gi1) ? 1.f : 0.f;
    }
#pragma unroll
    for (int k = 1; k <= 3; k++) {
        float rinv = 1.0f / (0.4f * (float)k);
#pragma unroll
        for (int i = 0; i + k < 11; i++) {
            float gi   = (i - 3) * 0.4f - 1.0f;          // g[i]
            float gik1 = (i + k - 2) * 0.4f - 1.0f;      // g[i+k+1]
            b[i] = (v - gi) * rinv * b[i] + (gik1 - v) * rinv * b[i + 1];
        }
    }
#pragma unroll
    for (int m = 0; m < 8; m++) b8[m] = b[m];
}

// ---------------------------------------------------------------------------
// Kernel 0: build G (per-conv 3x3x9 weights) and the 9 class-restricted
// composed 5x5 weight sets Hc[cls][m][du][dv]. cls = ri*3+rj where
// ri/rj in {0: on low edge, 1: interior, 2: on high edge}. Class restricts
// which restore-conv taps (u,v) correspond to in-image y positions.
// Single block so __syncthreads orders G before Hc.
// ---------------------------------------------------------------------------
__global__ void prep_kernel(const float* __restrict__ bw,   // [16,9]
                            const float* __restrict__ sw,   // [16,9,8]
                            const float* __restrict__ ss,   // [16,9]
                            const float* __restrict__ rw)   // [1,16,3,3]
{
    int t = threadIdx.x;
    for (int idx = t; idx < 16 * 81; idx += blockDim.x) {
        int c = idx / 81, r = idx % 81;
        int di = r / 27, dj = (r / 9) % 3, m = r % 9;
        int k = di * 3 + dj;
        float val;
        if (m == 0) val = bw[c * 9 + k];
        else        val = sw[(c * 9 + k) * 8 + (m - 1)] * ss[c * 9 + k];
        g_G[((c * 3 + di) * 3 + dj) * 9 + m] = val;
    }
    __syncthreads();
    for (int idx = t; idx < 9 * 225; idx += blockDim.x) {
        int cls = idx / 225, rem = idx % 225;
        int m = rem / 25, r = rem % 25;
        int du = r / 5, dv = r % 5;
        int ri = cls / 3, rj = cls % 3;
        float s = 0.f;
        for (int c = 0; c < 16; c++)
            for (int u = 0; u < 3; u++) {
                if (ri == 0 && u == 0) continue;   // i=0: y row above is padding
                if (ri == 2 && u == 2) continue;   // i=H-1
                int di = du - u; if (di < 0 || di > 2) continue;
                for (int v = 0; v < 3; v++) {
                    if (rj == 0 && v == 0) continue;
                    if (rj == 2 && v == 2) continue;
                    int dj = dv - v; if (dj < 0 || dj > 2) continue;
                    s += rw[(c * 3 + u) * 3 + v] * g_G[((c * 3 + di) * 3 + dj) * 9 + m];
                }
            }
        g_Hc[cls][m * 25 + r] = s;
    }
}

// ---------------------------------------------------------------------------
// Kernel 1: fused features + composed 5x5 conv (interior class), exact for
// all pixels at distance >= 1 from the border (border overwritten later).
// 64 threads/block, 4x4 micro-tile each, 32x32 block tile.
// Features computed on the fly from a 36x36 x-tile (x=0 for OOB -> exact
// padded features automatically).
// ---------------------------------------------------------------------------
__global__ void __launch_bounds__(64) main_kernel(const float* __restrict__ x,
                                                  float* __restrict__ out,
                                                  const float* __restrict__ rb)
{
    __shared__ float sF[9][36 * 36];   // 9 feature planes of the halo tile
    __shared__ float sH[225];

    int t  = threadIdx.x;
    int tx = t & 7, ty = t >> 3;
    int gx0 = blockIdx.x * 32, gy0 = blockIdx.y * 32;
    int bz = blockIdx.z;

    for (int i = t; i < 225; i += 64) sH[i] = g_Hc[4][i];   // interior class

    const float* xp = x + (size_t)bz * HWp;
    for (int idx = t; idx < 36 * 36; idx += 64) {
        int r = idx / 36, c2 = idx - r * 36;
        int gy = gy0 - 2 + r, gx = gx0 - 2 + c2;
        float v = 0.f;
        if (gy >= 0 && gy < Hdim && gx >= 0 && gx < Wdim)
            v = __ldg(&xp[gy * Wdim + gx]);
        float sig = 1.0f / (1.0f + expf(-v));
        sF[0][idx] = v * sig;
        float b8[8];
        spline_bases(v, b8);
#pragma unroll
        for (int m = 0; m < 8; m++) sF[m + 1][idx] = b8[m];
    }
    __syncthreads();

    float acc[4][4] = {};
#pragma unroll 1
    for (int m = 0; m < 9; m++) {
        float win[8][8];
#pragma unroll
        for (int dy = 0; dy < 8; dy++) {
            const float* row = &sF[m][(ty * 4 + dy) * 36 + tx * 4];
            float4 a  = *(const float4*)(row);
            float4 bq = *(const float4*)(row + 4);
            win[dy][0] = a.x;  win[dy][1] = a.y;  win[dy][2] = a.z;  win[dy][3] = a.w;
            win[dy][4] = bq.x; win[dy][5] = bq.y; win[dy][6] = bq.z; win[dy][7] = bq.w;
        }
        const float* Hm = &sH[m * 25];
#pragma unroll
        for (int du = 0; du < 5; du++)
#pragma unroll
            for (int dv = 0; dv < 5; dv++) {
                float h = Hm[du * 5 + dv];
#pragma unroll
                for (int ry = 0; ry < 4; ry++)
#pragma unroll
                    for (int rx = 0; rx < 4; rx++)
                        acc[ry][rx] = fmaf(h, win[ry + du][rx + dv], acc[ry][rx]);
            }
    }

    float rbv = __ldg(rb);
    float* op = out + (size_t)bz * HWp;
#pragma unroll
    for (int ry = 0; ry < 4; ry++) {
        int oy = gy0 + ty * 4 + ry;
        float4 o;
        o.x = acc[ry][0] + rbv; o.y = acc[ry][1] + rbv;
        o.z = acc[ry][2] + rbv; o.w = acc[ry][3] + rbv;
        *(float4*)&op[(size_t)oy * Wdim + gx0 + tx * 4] = o;
    }
}

// ---------------------------------------------------------------------------
// Kernel 2: border ring (width 1), one thread per pixel. Uses the class-
// restricted composed weights Hc[cls] over on-the-fly features of the 5x5
// x-neighborhood (x=0 OOB). Exact.
// ---------------------------------------------------------------------------
__global__ void border_kernel(const float* __restrict__ x,
                              float* __restrict__ out,
                              const float* __restrict__ rb)
{
    int pix = blockIdx.x * blockDim.x + threadIdx.x;
    if (pix >= NBORD) return;
    int b = pix / PER_IMG, e = pix % PER_IMG;
    int i, j;
    if (e < Wdim)            { i = 0;        j = e; }
    else if (e < 2 * Wdim)   { i = Hdim - 1; j = e - Wdim; }
    else if (e < 2 * Wdim + (Hdim - 2)) { i = e - 2 * Wdim + 1; j = 0; }
    else                     { i = e - (2 * Wdim + (Hdim - 2)) + 1; j = Wdim - 1; }

    int ri = (i == 0) ? 0 : ((i == Hdim - 1) ? 2 : 1);
    int rj = (j == 0) ? 0 : ((j == Wdim - 1) ? 2 : 1);
    const float* Hc = g_Hc[ri * 3 + rj];
    const float* xp = x + (size_t)b * HWp;

    float acc = 0.f;
#pragma unroll
    for (int du = 0; du < 5; du++) {
        int fy = i + du - 2;
#pragma unroll
        for (int dv = 0; dv < 5; dv++) {
            int fx = j + dv - 2;
            float v = 0.f;
            if (fy >= 0 && fy < Hdim && fx >= 0 && fx < Wdim)
                v = __ldg(&xp[fy * Wdim + fx]);
            float sig = 1.0f / (1.0f + expf(-v));
            float f0 = v * sig;
            float b8[8];
            spline_bases(v, b8);
            int pos = du * 5 + dv;
            acc = fmaf(__ldg(&Hc[pos]), f0, acc);
#pragma unroll
            for (int m = 0; m < 8; m++)
                acc = fmaf(__ldg(&Hc[(m + 1) * 25 + pos]), b8[m], acc);
        }
    }
    out[(size_t)b * HWp + (size_t)i * Wdim + j] = acc + __ldg(rb);
}

// ---------------------------------------------------------------------------
extern "C" void kernel_launch(void* const* d_in, const int* in_sizes, int n_in,
                              void* d_out, int out_size)
{
    const float* x  = (const float*)d_in[0];
    const float* bw = (const float*)d_in[1];
    const float* sw = (const float*)d_in[2];
    const float* ss = (const float*)d_in[3];
    const float* rw = (const float*)d_in[4];
    const float* rb = (const float*)d_in[5];
    float* out = (float*)d_out;

    prep_kernel<<<1, 256>>>(bw, sw, ss, rw);
    dim3 grid(Wdim / 32, Hdim / 32, BATCH);
    main_kernel<<<grid, 64>>>(x, out, rb);
    border_kernel<<<(NBORD + 127) / 128, 128>>>(x, out, rb);
}

// round 4
// speedup vs baseline: 3.1212x; 1.6379x over previous
#include <cuda_runtime.h>
#include <math.h>

#define Hdim 384
#define Wdim 384
#define HWp  (Hdim*Wdim)
#define BATCH 8
#define PER_IMG (2*Wdim + 2*(Hdim-2))   // 1532 border pixels per image
#define NBORD  (BATCH*PER_IMG)

// per-border-class composed weights [cls][m][du*5+dv]; cls=4 is interior
__device__ float g_Hc[9][9 * 25];

// Cox-de Boor cubic bases (exact recursion; used by prep + border only)
__device__ __forceinline__ void spline_bases(float v, float* b8)
{
    float b[11];
#pragma unroll
    for (int i = 0; i < 11; i++) {
        float gi  = (i - 3) * 0.4f - 1.0f;
        float gi1 = (i - 2) * 0.4f - 1.0f;
        b[i] = (v >= gi && v < gi1) ? 1.f : 0.f;
    }
#pragma unroll
    for (int k = 1; k <= 3; k++) {
        float rinv = 1.0f / (0.4f * (float)k);
#pragma unroll
        for (int i = 0; i + k < 11; i++) {
            float gi   = (i - 3) * 0.4f - 1.0f;
            float gik1 = (i + k - 2) * 0.4f - 1.0f;
            b[i] = (v - gi) * rinv * b[i] + (gik1 - v) * rinv * b[i + 1];
        }
    }
#pragma unroll
    for (int m = 0; m < 8; m++) b8[m] = b[m];
}

// ---------------------------------------------------------------------------
// Kernel 0: build G in SMEM, then the 9 class-restricted composed 5x5 weight
// sets Hc[cls][m][du][dv]. All inner reads hit shared memory.
// ---------------------------------------------------------------------------
__global__ void prep_kernel(const float* __restrict__ bw,   // [16,9]
                            const float* __restrict__ sw,   // [16,9,8]
                            const float* __restrict__ ss,   // [16,9]
                            const float* __restrict__ rw)   // [1,16,3,3]
{
    __shared__ float sG[16 * 81];   // G[c][di][dj][m]
    __shared__ float srw[144];
    int t = threadIdx.x;

    if (t < 144) srw[t] = rw[t];
    for (int idx = t; idx < 16 * 81; idx += blockDim.x) {
        int c = idx / 81, r = idx % 81;
        int di = r / 27, dj = (r / 9) % 3, m = r % 9;
        int k = di * 3 + dj;
        float val;
        if (m == 0) val = bw[c * 9 + k];
        else        val = sw[(c * 9 + k) * 8 + (m - 1)] * ss[c * 9 + k];
        sG[((c * 3 + di) * 3 + dj) * 9 + m] = val;
    }
    __syncthreads();

    for (int idx = t; idx < 9 * 225; idx += blockDim.x) {
        int cls = idx / 225, rem = idx % 225;
        int m = rem / 25, r = rem % 25;
        int du = r / 5, dv = r % 5;
        int ri = cls / 3, rj = cls % 3;
        float s = 0.f;
        for (int u = 0; u < 3; u++) {
            if (ri == 0 && u == 0) continue;
            if (ri == 2 && u == 2) continue;
            int di = du - u; if (di < 0 || di > 2) continue;
            for (int v = 0; v < 3; v++) {
                if (rj == 0 && v == 0) continue;
                if (rj == 2 && v == 2) continue;
                int dj = dv - v; if (dj < 0 || dj > 2) continue;
                for (int c = 0; c < 16; c++)
                    s += srw[(c * 3 + u) * 3 + v] * sG[((c * 3 + di) * 3 + dj) * 9 + m];
            }
        }
        g_Hc[cls][m * 25 + r] = s;
    }
}

// ---------------------------------------------------------------------------
// Kernel 1: fused features + composed 5x5 conv (interior class).
// 128 threads/block, 2x4 micro-tile, 32x32 block tile, 36x36 halo.
// Features via closed-form cardinal cubic B-spline (<=4 nonzero bases).
// ---------------------------------------------------------------------------
__global__ void __launch_bounds__(128) main_kernel(const float* __restrict__ x,
                                                   float* __restrict__ out,
                                                   const float* __restrict__ rb)
{
    __shared__ float sF[9][36 * 36];   // 9 feature planes of the halo tile
    __shared__ float sH[225];

    int t  = threadIdx.x;
    int tx = t & 7, ty = t >> 3;        // 8 x 16 threads
    int gx0 = blockIdx.x * 32, gy0 = blockIdx.y * 32;
    int bz = blockIdx.z;

    for (int i = t; i < 225; i += 128) sH[i] = g_Hc[4][i];

    const float* xp = x + (size_t)bz * HWp;
    for (int idx = t; idx < 36 * 36; idx += 128) {
        int r = idx / 36, c2 = idx - r * 36;
        int gy = gy0 - 2 + r, gx = gx0 - 2 + c2;
        float v = 0.f;
        if (gy >= 0 && gy < Hdim && gx >= 0 && gx < Wdim)
            v = __ldg(&xp[gy * Wdim + gx]);

        float sig = 1.0f / (1.0f + __expf(-v));
        sF[0][idx] = v * sig;
#pragma unroll
        for (int m = 1; m < 9; m++) sF[m][idx] = 0.f;

        // interval index on knots g_i = 0.4*i - 2.2 (i = 0..11)
        float s  = (v + 2.2f) * 2.5f;
        float tf = floorf(s);
        int   ti = (int)tf;
        if (ti >= 0 && ti <= 10) {
            float gt = tf * 0.4f - 2.2f;
            float u  = (v - gt) * 2.5f;
            float u1 = 1.0f - u;
            float u2 = u * u, u12 = u1 * u1;
            const float c6 = 1.0f / 6.0f;
            float w0 = u12 * u1 * c6;                       // base ti-3
            float w1 = (3.f*u2*u - 6.f*u2 + 4.f) * c6;      // base ti-2
            float w2 = (-3.f*u2*u + 3.f*u2 + 3.f*u + 1.f) * c6; // base ti-1
            float w3 = u2 * u * c6;                         // base ti
            int m0 = ti - 3;
            if (m0     >= 0 && m0     <= 7) sF[m0 + 1][idx] = w0;
            if (m0 + 1 >= 0 && m0 + 1 <= 7) sF[m0 + 2][idx] = w1;
            if (m0 + 2 >= 0 && m0 + 2 <= 7) sF[m0 + 3][idx] = w2;
            if (ti     >= 0 && ti     <= 7) sF[ti + 1][idx] = w3;
        }
    }
    __syncthreads();

    float acc[2][4] = {};
#pragma unroll 1
    for (int m = 0; m < 9; m++) {
        float win[6][8];
#pragma unroll
        for (int dy = 0; dy < 6; dy++) {
            const float* row = &sF[m][(ty * 2 + dy) * 36 + tx * 4];
            float4 a  = *(const float4*)(row);
            float4 bq = *(const float4*)(row + 4);
            win[dy][0] = a.x;  win[dy][1] = a.y;  win[dy][2] = a.z;  win[dy][3] = a.w;
            win[dy][4] = bq.x; win[dy][5] = bq.y; win[dy][6] = bq.z; win[dy][7] = bq.w;
        }
        const float* Hm = &sH[m * 25];
#pragma unroll
        for (int du = 0; du < 5; du++)
#pragma unroll
            for (int dv = 0; dv < 5; dv++) {
                float h = Hm[du * 5 + dv];
#pragma unroll
                for (int ry = 0; ry < 2; ry++)
#pragma unroll
                    for (int rx = 0; rx < 4; rx++)
                        acc[ry][rx] = fmaf(h, win[ry + du][rx + dv], acc[ry][rx]);
            }
    }

    float rbv = __ldg(rb);
    float* op = out + (size_t)bz * HWp;
#pragma unroll
    for (int ry = 0; ry < 2; ry++) {
        int oy = gy0 + ty * 2 + ry;
        float4 o;
        o.x = acc[ry][0] + rbv; o.y = acc[ry][1] + rbv;
        o.z = acc[ry][2] + rbv; o.w = acc[ry][3] + rbv;
        *(float4*)&op[(size_t)oy * Wdim + gx0 + tx * 4] = o;
    }
}

// ---------------------------------------------------------------------------
// Kernel 2: border ring (width 1), one thread per pixel, class-restricted
// composed weights over on-the-fly features of the 5x5 x-neighborhood.
// ---------------------------------------------------------------------------
__global__ void border_kernel(const float* __restrict__ x,
                              float* __restrict__ out,
                              const float* __restrict__ rb)
{
    int pix = blockIdx.x * blockDim.x + threadIdx.x;
    if (pix >= NBORD) return;
    int b = pix / PER_IMG, e = pix % PER_IMG;
    int i, j;
    if (e < Wdim)            { i = 0;        j = e; }
    else if (e < 2 * Wdim)   { i = Hdim - 1; j = e - Wdim; }
    else if (e < 2 * Wdim + (Hdim - 2)) { i = e - 2 * Wdim + 1; j = 0; }
    else                     { i = e - (2 * Wdim + (Hdim - 2)) + 1; j = Wdim - 1; }

    int ri = (i == 0) ? 0 : ((i == Hdim - 1) ? 2 : 1);
    int rj = (j == 0) ? 0 : ((j == Wdim - 1) ? 2 : 1);
    const float* Hc = g_Hc[ri * 3 + rj];
    const float* xp = x + (size_t)b * HWp;

    float acc = 0.f;
#pragma unroll
    for (int du = 0; du < 5; du++) {
        int fy = i + du - 2;
#pragma unroll
        for (int dv = 0; dv < 5; dv++) {
            int fx = j + dv - 2;
            float v = 0.f;
            if (fy >= 0 && fy < Hdim && fx >= 0 && fx < Wdim)
                v = __ldg(&xp[fy * Wdim + fx]);
            float sig = 1.0f / (1.0f + __expf(-v));
            float f0 = v * sig;
            float b8[8];
            spline_bases(v, b8);
            int pos = du * 5 + dv;
            acc = fmaf(__ldg(&Hc[pos]), f0, acc);
#pragma unroll
            for (int m = 0; m < 8; m++)
                acc = fmaf(__ldg(&Hc[(m + 1) * 25 + pos]), b8[m], acc);
        }
    }
    out[(size_t)b * HWp + (size_t)i * Wdim + j] = acc + __ldg(rb);
}

// ---------------------------------------------------------------------------
extern "C" void kernel_launch(void* const* d_in, const int* in_sizes, int n_in,
                              void* d_out, int out_size)
{
    const float* x  = (const float*)d_in[0];
    const float* bw = (const float*)d_in[1];
    const float* sw = (const float*)d_in[2];
    const float* ss = (const float*)d_in[3];
    const float* rw = (const float*)d_in[4];
    const float* rb = (const float*)d_in[5];
    float* out = (float*)d_out;

    prep_kernel<<<1, 256>>>(bw, sw, ss, rw);
    dim3 grid(Wdim / 32, Hdim / 32, BATCH);
    main_kernel<<<grid, 128>>>(x, out, rb);
    border_kernel<<<(NBORD + 127) / 128, 128>>>(x, out, rb);
}

// round 5
// speedup vs baseline: 3.4136x; 1.0937x over previous
#include <cuda_runtime.h>
#include <math.h>

#define Hdim 384
#define Wdim 384
#define HWp  (Hdim*Wdim)
#define BATCH 8
#define PER_IMG (2*Wdim + 2*(Hdim-2))   // 1532 border pixels per image
#define NBORD  (BATCH*PER_IMG)

typedef unsigned long long u64;

// per-border-class composed weights [cls][m][du*5+dv]; cls=4 is interior
__device__ float  g_Hc[9][9 * 25];
__device__ float2 g_H2[9 * 25];          // interior weights duplicated (h,h)

__device__ __forceinline__ u64 fma2(u64 a, u64 b, u64 c) {
    u64 d;
    asm("fma.rn.f32x2 %0, %1, %2, %3;" : "=l"(d) : "l"(a), "l"(b), "l"(c));
    return d;
}
__device__ __forceinline__ u64 pack2(float lo, float hi) {
    u64 d;
    asm("mov.b64 %0, {%1, %2};" : "=l"(d)
        : "r"(__float_as_uint(lo)), "r"(__float_as_uint(hi)));
    return d;
}
__device__ __forceinline__ void unpack2(u64 v, float& lo, float& hi) {
    unsigned int a, b;
    asm("mov.b64 {%0, %1}, %2;" : "=r"(a), "=r"(b) : "l"(v));
    lo = __uint_as_float(a); hi = __uint_as_float(b);
}

// Cox-de Boor cubic bases (exact recursion; border kernel only)
__device__ __forceinline__ void spline_bases(float v, float* b8)
{
    float b[11];
#pragma unroll
    for (int i = 0; i < 11; i++) {
        float gi  = (i - 3) * 0.4f - 1.0f;
        float gi1 = (i - 2) * 0.4f - 1.0f;
        b[i] = (v >= gi && v < gi1) ? 1.f : 0.f;
    }
#pragma unroll
    for (int k = 1; k <= 3; k++) {
        float rinv = 1.0f / (0.4f * (float)k);
#pragma unroll
        for (int i = 0; i + k < 11; i++) {
            float gi   = (i - 3) * 0.4f - 1.0f;
            float gik1 = (i + k - 2) * 0.4f - 1.0f;
            b[i] = (v - gi) * rinv * b[i] + (gik1 - v) * rinv * b[i + 1];
        }
    }
#pragma unroll
    for (int m = 0; m < 8; m++) b8[m] = b[m];
}

// ---------------------------------------------------------------------------
// Kernel 0: 9 blocks, one border class each. Build G in SMEM, one composed
// weight per thread (225 outputs/class), 2-way ILP accumulation.
// ---------------------------------------------------------------------------
__global__ void prep_kernel(const float* __restrict__ bw,   // [16,9]
                            const float* __restrict__ sw,   // [16,9,8]
                            const float* __restrict__ ss,   // [16,9]
                            const float* __restrict__ rw)   // [1,16,3,3]
{
    __shared__ float sG[16 * 81];   // G[c][di][dj][m]
    __shared__ float srw[144];
    int t = threadIdx.x;
    int cls = blockIdx.x;

    if (t < 144) srw[t] = rw[t];
    for (int idx = t; idx < 16 * 81; idx += blockDim.x) {
        int c = idx / 81, r = idx % 81;
        int di = r / 27, dj = (r / 9) % 3, m = r % 9;
        int k = di * 3 + dj;
        float val;
        if (m == 0) val = bw[c * 9 + k];
        else        val = sw[(c * 9 + k) * 8 + (m - 1)] * ss[c * 9 + k];
        sG[((c * 3 + di) * 3 + dj) * 9 + m] = val;
    }
    __syncthreads();

    if (t < 225) {
        int m = t / 25, r = t % 25;
        int du = r / 5, dv = r % 5;
        int ri = cls / 3, rj = cls % 3;
        float s0 = 0.f, s1 = 0.f;
        for (int u = 0; u < 3; u++) {
            if (ri == 0 && u == 0) continue;
            if (ri == 2 && u == 2) continue;
            int di = du - u; if (di < 0 || di > 2) continue;
            for (int v = 0; v < 3; v++) {
                if (rj == 0 && v == 0) continue;
                if (rj == 2 && v == 2) continue;
                int dj = dv - v; if (dj < 0 || dj > 2) continue;
#pragma unroll
                for (int c = 0; c < 16; c += 2) {
                    s0 = fmaf(srw[(c * 3 + u) * 3 + v],
                              sG[((c * 3 + di) * 3 + dj) * 9 + m], s0);
                    s1 = fmaf(srw[((c + 1) * 3 + u) * 3 + v],
                              sG[(((c + 1) * 3 + di) * 3 + dj) * 9 + m], s1);
                }
            }
        }
        float s = s0 + s1;
        g_Hc[cls][t] = s;
        if (cls == 4) g_H2[t] = make_float2(s, s);
    }
}

// ---------------------------------------------------------------------------
// Kernel 1: fused features + composed 5x5 conv (interior class).
// 128 threads/block, 2x4 micro-tile, 32x32 block tile, 36x36 halo.
// Conv inner loop uses packed fma.rn.f32x2 (2 output columns per pair).
// ---------------------------------------------------------------------------
__global__ void __launch_bounds__(128) main_kernel(const float* __restrict__ x,
                                                   float* __restrict__ out,
                                                   const float* __restrict__ rb)
{
    __shared__ float sF[9][36 * 36];   // 9 feature planes of the halo tile
    __shared__ u64   sH2[225];         // (h,h) duplicated weights

    int t  = threadIdx.x;
    int tx = t & 7, ty = t >> 3;        // 8 x 16 threads
    int gx0 = blockIdx.x * 32, gy0 = blockIdx.y * 32;
    int bz = blockIdx.z;

    {
        const u64* src = (const u64*)g_H2;
        for (int i = t; i < 225; i += 128) sH2[i] = src[i];
    }

    const float* xp = x + (size_t)bz * HWp;
    for (int idx = t; idx < 36 * 36; idx += 128) {
        int r = idx / 36, c2 = idx - r * 36;
        int gy = gy0 - 2 + r, gx = gx0 - 2 + c2;
        float v = 0.f;
        if (gy >= 0 && gy < Hdim && gx >= 0 && gx < Wdim)
            v = __ldg(&xp[gy * Wdim + gx]);

        float sig = 1.0f / (1.0f + __expf(-v));
        sF[0][idx] = v * sig;
#pragma unroll
        for (int m = 1; m < 9; m++) sF[m][idx] = 0.f;

        // interval index on knots g_i = 0.4*i - 2.2 (i = 0..11)
        float sc = (v + 2.2f) * 2.5f;
        float tf = floorf(sc);
        int   ti = (int)tf;
        if (ti >= 0 && ti <= 10) {
            float gt = tf * 0.4f - 2.2f;
            float u  = (v - gt) * 2.5f;
            float u1 = 1.0f - u;
            float u2 = u * u, u12 = u1 * u1;
            const float c6 = 1.0f / 6.0f;
            float w0 = u12 * u1 * c6;
            float w1 = (3.f*u2*u - 6.f*u2 + 4.f) * c6;
            float w2 = (-3.f*u2*u + 3.f*u2 + 3.f*u + 1.f) * c6;
            float w3 = u2 * u * c6;
            int m0 = ti - 3;
            if (m0     >= 0 && m0     <= 7) sF[m0 + 1][idx] = w0;
            if (m0 + 1 >= 0 && m0 + 1 <= 7) sF[m0 + 2][idx] = w1;
            if (m0 + 2 >= 0 && m0 + 2 <= 7) sF[m0 + 3][idx] = w2;
            if (ti     >= 0 && ti     <= 7) sF[ti + 1][idx] = w3;
        }
    }
    __syncthreads();

    // Packed accumulators: A[ry][p] = (out[ry][2p], out[ry][2p+1])
    u64 A00 = 0, A01 = 0, A10 = 0, A11 = 0;

#pragma unroll 1
    for (int m = 0; m < 9; m++) {
#pragma unroll
        for (int r = 0; r < 6; r++) {
            const float* row = &sF[m][(ty * 2 + r) * 36 + tx * 4];
            float4 a  = *(const float4*)(row);
            float4 b4 = *(const float4*)(row + 4);
            u64 P[7];
            P[0] = pack2(a.x, a.y);  P[1] = pack2(a.y, a.z);
            P[2] = pack2(a.z, a.w);  P[3] = pack2(a.w, b4.x);
            P[4] = pack2(b4.x, b4.y); P[5] = pack2(b4.y, b4.z);
            P[6] = pack2(b4.z, b4.w);
            if (r < 5) {                 // consumer ry=0, du=r
#pragma unroll
                for (int dv = 0; dv < 5; dv++) {
                    u64 hh = sH2[m * 25 + r * 5 + dv];
                    A00 = fma2(P[dv],     hh, A00);
                    A01 = fma2(P[dv + 2], hh, A01);
                }
            }
            if (r >= 1) {                // consumer ry=1, du=r-1
#pragma unroll
                for (int dv = 0; dv < 5; dv++) {
                    u64 hh = sH2[m * 25 + (r - 1) * 5 + dv];
                    A10 = fma2(P[dv],     hh, A10);
                    A11 = fma2(P[dv + 2], hh, A11);
                }
            }
        }
    }

    float rbv = __ldg(rb);
    float* op = out + (size_t)bz * HWp;
    float o0, o1, o2, o3;
    {
        int oy = gy0 + ty * 2;
        float4 o;
        unpack2(A00, o0, o1); unpack2(A01, o2, o3);
        o.x = o0 + rbv; o.y = o1 + rbv; o.z = o2 + rbv; o.w = o3 + rbv;
        *(float4*)&op[(size_t)oy * Wdim + gx0 + tx * 4] = o;
        unpack2(A10, o0, o1); unpack2(A11, o2, o3);
        o.x = o0 + rbv; o.y = o1 + rbv; o.z = o2 + rbv; o.w = o3 + rbv;
        *(float4*)&op[(size_t)(oy + 1) * Wdim + gx0 + tx * 4] = o;
    }
}

// ---------------------------------------------------------------------------
// Kernel 2: border ring (width 1), one thread per pixel, class-restricted
// composed weights over on-the-fly features of the 5x5 x-neighborhood.
// ---------------------------------------------------------------------------
__global__ void border_kernel(const float* __restrict__ x,
                              float* __restrict__ out,
                              const float* __restrict__ rb)
{
    int pix = blockIdx.x * blockDim.x + threadIdx.x;
    if (pix >= NBORD) return;
    int b = pix / PER_IMG, e = pix % PER_IMG;
    int i, j;
    if (e < Wdim)            { i = 0;        j = e; }
    else if (e < 2 * Wdim)   { i = Hdim - 1; j = e - Wdim; }
    else if (e < 2 * Wdim + (Hdim - 2)) { i = e - 2 * Wdim + 1; j = 0; }
    else                     { i = e - (2 * Wdim + (Hdim - 2)) + 1; j = Wdim - 1; }

    int ri = (i == 0) ? 0 : ((i == Hdim - 1) ? 2 : 1);
    int rj = (j == 0) ? 0 : ((j == Wdim - 1) ? 2 : 1);
    const float* Hc = g_Hc[ri * 3 + rj];
    const float* xp = x + (size_t)b * HWp;

    float acc = 0.f;
#pragma unroll
    for (int du = 0; du < 5; du++) {
        int fy = i + du - 2;
#pragma unroll
        for (int dv = 0; dv < 5; dv++) {
            int fx = j + dv - 2;
            float v = 0.f;
            if (fy >= 0 && fy < Hdim && fx >= 0 && fx < Wdim)
                v = __ldg(&xp[fy * Wdim + fx]);
            float sig = 1.0f / (1.0f + __expf(-v));
            float f0 = v * sig;
            float b8[8];
            spline_bases(v, b8);
            int pos = du * 5 + dv;
            acc = fmaf(__ldg(&Hc[pos]), f0, acc);
#pragma unroll
            for (int m = 0; m < 8; m++)
                acc = fmaf(__ldg(&Hc[(m + 1) * 25 + pos]), b8[m], acc);
        }
    }
    out[(size_t)b * HWp + (size_t)i * Wdim + j] = acc + __ldg(rb);
}

// ---------------------------------------------------------------------------
extern "C" void kernel_launch(void* const* d_in, const int* in_sizes, int n_in,
                              void* d_out, int out_size)
{
    const float* x  = (const float*)d_in[0];
    const float* bw = (const float*)d_in[1];
    const float* sw = (const float*)d_in[2];
    const float* ss = (const float*)d_in[3];
    const float* rw = (const float*)d_in[4];
    const float* rb = (const float*)d_in[5];
    float* out = (float*)d_out;

    prep_kernel<<<9, 256>>>(bw, sw, ss, rw);
    dim3 grid(Wdim / 32, Hdim / 32, BATCH);
    main_kernel<<<grid, 128>>>(x, out, rb);
    border_kernel<<<(NBORD + 127) / 128, 128>>>(x, out, rb);
}